// round 6
// baseline (speedup 1.0000x reference)
#include <cuda_runtime.h>
#include <cuda_bf16.h>
#include <cstdint>

#define M_MATCH 5000
#define TOT     10000
#define CF      128
#define CC      256
#define WW      25
#define LCELLS  4800
#define HFD     240
#define WFD     320

typedef unsigned long long ull;

__device__ float g_t[TOT * CF];     // proj result t[m][o]
__device__ float g_Wc[CC * CF];     // fused (W2@Wd)^T, [c][o]
__device__ float g_bc[CF];

__device__ __forceinline__ uint32_t smem_u32(const void* p) {
    uint32_t a;
    asm("{ .reg .u64 t; cvta.to.shared.u64 t, %1; cvt.u32.u64 %0, t; }" : "=r"(a) : "l"(p));
    return a;
}

#define LDSM_X4(r0, r1, r2, r3, addr)                                          \
    asm volatile("ldmatrix.sync.aligned.m8n8.x4.shared.b16 {%0,%1,%2,%3}, [%4];" \
        : "=r"(r0), "=r"(r1), "=r"(r2), "=r"(r3) : "r"(addr))

#define MMA16816(d, a0, a1, a2, a3, b0, b1)                                    \
    asm volatile("mma.sync.aligned.m16n8k16.row.col.f32.bf16.bf16.f32 "        \
        "{%0,%1,%2,%3}, {%4,%5,%6,%7}, {%8,%9}, {%0,%1,%2,%3};"                \
        : "+f"((d)[0]), "+f"((d)[1]), "+f"((d)[2]), "+f"((d)[3])               \
        : "r"(a0), "r"(a1), "r"(a2), "r"(a3), "r"(b0), "r"(b1))

// ---------------------------------------------------------------------------
// Kernel -1: no-op (shifts ncu capture alignment to land on fine_kernel)
// ---------------------------------------------------------------------------
__global__ void warmup_kernel() {}

// ---------------------------------------------------------------------------
// Kernel 0 (parallel): Wc[c][o] = sum_j Wd[j][c]*W2[o][j];  bc = W2@bd + bm
// 128 blocks x 128 thr; block b computes c = b and c = b+128.
// Wd reads are lane-uniform (broadcast); W2 staged transposed in smem.
// ---------------------------------------------------------------------------
__global__ void __launch_bounds__(128)
wc_kernel(const float* __restrict__ Wd, const float* __restrict__ bd,
          const float* __restrict__ Wm, const float* __restrict__ bm)
{
    extern __shared__ float w2T[];   // [j][129]
    const int tid = threadIdx.x;     // = o
    const int c = blockIdx.x;

    for (int it = 0; it < 128; it++)
        w2T[tid * 129 + it] = Wm[it * 256 + 128 + tid];  // w2T[j=tid? no:]
    // NOTE: loop above loads Wm[o'=it][128+tid] into w2T[tid*129+it]:
    //   w2T[j][o'] layout with j=tid row... we want w2T[j*129+o]. Redo properly:
    __syncthreads();
    // Overwrite with correct orientation (cheap; keeps loads coalesced):
    for (int it = 0; it < 128; it++) {
        // thread tid reads Wm[it*256 + 128 + tid] = W2[o=it][j=tid]
        // store to w2T[j=tid][o=it]
        w2T[tid * 129 + it] = Wm[it * 256 + 128 + tid];
    }
    __syncthreads();

    float a0 = 0.f, a1 = 0.f;
    #pragma unroll 4
    for (int j = 0; j < 128; j++) {
        float w2 = w2T[j * 129 + tid];          // w2T[j][o=tid]
        a0 += __ldg(&Wd[j * 256 + c])       * w2;
        a1 += __ldg(&Wd[j * 256 + c + 128]) * w2;
    }
    g_Wc[(size_t)c * 128 + tid]         = a0;
    g_Wc[(size_t)(c + 128) * 128 + tid] = a1;

    if (blockIdx.x == 0) {
        float acc = bm[tid];
        #pragma unroll 4
        for (int j = 0; j < 128; j++)
            acc += w2T[j * 129 + tid] * __ldg(&bd[j]);
        g_bc[tid] = acc;
    }
}

// ---------------------------------------------------------------------------
// Kernel 1: t[10000,128] = gather(feat_c) @ Wc + bc   (unchanged from R5)
// ---------------------------------------------------------------------------
__global__ void __launch_bounds__(256, 2)
proj_kernel(const float* __restrict__ feat_c0, const float* __restrict__ feat_c1,
            const int* __restrict__ b_ids, const int* __restrict__ i_ids,
            const int* __restrict__ j_ids)
{
    extern __shared__ char sraw[];
    float* A   = (float*)sraw;                       // [64][64]
    float* Wcs = (float*)(sraw + 16384);             // [64][128]
    const float** srow = (const float**)(sraw + 16384 + 32768);

    const int tid = threadIdx.x;
    const int tile = blockIdx.x;
    const int og = tid & 15, rg = tid >> 4;
    const int o0 = og * 8;

    if (tid < 64) {
        int m = tile * 64 + tid;
        const float* p = nullptr;
        if (m < TOT) {
            int mm = (m < M_MATCH) ? m : m - M_MATCH;
            int b  = b_ids[mm];
            int l  = (m < M_MATCH) ? i_ids[mm] : j_ids[mm];
            p = ((m < M_MATCH) ? feat_c0 : feat_c1) + ((size_t)b * LCELLS + l) * CC;
        }
        srow[tid] = p;
    }

    float acc[4][8];
    {
        float4 bA = *(const float4*)&g_bc[o0];
        float4 bB = *(const float4*)&g_bc[o0 + 4];
        #pragma unroll
        for (int j = 0; j < 4; j++) {
            acc[j][0] = bA.x; acc[j][1] = bA.y; acc[j][2] = bA.z; acc[j][3] = bA.w;
            acc[j][4] = bB.x; acc[j][5] = bB.y; acc[j][6] = bB.z; acc[j][7] = bB.w;
        }
    }
    __syncthreads();

    for (int kc = 0; kc < 256; kc += 64) {
        for (int e = tid; e < 64 * 64; e += 256) {
            const float* p = srow[e >> 6];
            A[e] = p ? __ldg(p + kc + (e & 63)) : 0.f;
        }
        for (int e = tid; e < 64 * 128; e += 256)
            Wcs[e] = g_Wc[(size_t)(kc + (e >> 7)) * 128 + (e & 127)];
        __syncthreads();

        #pragma unroll 2
        for (int k = 0; k < 64; k += 4) {
            float4 fv[4];
            #pragma unroll
            for (int j = 0; j < 4; j++)
                fv[j] = *(const float4*)&A[(rg + 16 * j) * 64 + k];
            #define PSTEP(kk, COMP)                                            \
            {                                                                  \
                float4 wA = *(const float4*)&Wcs[(k + kk) * 128 + o0];         \
                float4 wB = *(const float4*)&Wcs[(k + kk) * 128 + o0 + 4];     \
                _Pragma("unroll")                                              \
                for (int j = 0; j < 4; j++) {                                  \
                    float a = fv[j].COMP;                                      \
                    acc[j][0] += a * wA.x; acc[j][1] += a * wA.y;              \
                    acc[j][2] += a * wA.z; acc[j][3] += a * wA.w;              \
                    acc[j][4] += a * wB.x; acc[j][5] += a * wB.y;              \
                    acc[j][6] += a * wB.z; acc[j][7] += a * wB.w;              \
                }                                                              \
            }
            PSTEP(0, x) PSTEP(1, y) PSTEP(2, z) PSTEP(3, w)
            #undef PSTEP
        }
        __syncthreads();
    }

    #pragma unroll
    for (int j = 0; j < 4; j++) {
        int m = tile * 64 + rg + 16 * j;
        if (m < TOT) {
            float* dst = &g_t[(size_t)m * CF + o0];
            *(float4*)dst       = make_float4(acc[j][0], acc[j][1], acc[j][2], acc[j][3]);
            *(float4*)(dst + 4) = make_float4(acc[j][4], acc[j][5], acc[j][6], acc[j][7]);
        }
    }
}

// ---------------------------------------------------------------------------
// Kernel 2: fine gather + HMMA merge GEMM (unchanged from R5 — baseline probe)
// ---------------------------------------------------------------------------
#define APITCH 136
#define ABYTES (128 * APITCH * 2)

__global__ void __launch_bounds__(256)
fine_kernel(const float* __restrict__ feat_f0, const float* __restrict__ feat_f1,
            const int* __restrict__ b_ids, const int* __restrict__ i_ids,
            const int* __restrict__ j_ids,
            const float* __restrict__ Wm, float* __restrict__ out)
{
    extern __shared__ char sraw[];
    char* Ah = sraw;
    char* Al = sraw + ABYTES;
    char* Bh = sraw + 2 * ABYTES;
    char* Bl = sraw + 3 * ABYTES;
    float* t_s = (float*)(sraw + 4 * ABYTES);
    int*   sl  = (int*)(sraw + 4 * ABYTES + 2560);
    ull*   sfb = (ull*)(sraw + 4 * ABYTES + 2592);

    const uint32_t sAh = smem_u32(Ah);
    const uint32_t sAl = smem_u32(Al);
    const uint32_t sBh = smem_u32(Bh);
    const uint32_t sBl = smem_u32(Bl);

    const int tid = threadIdx.x;
    const int wid = tid >> 5;
    const int lane = tid & 31;

    for (int e2 = tid; e2 < 8192; e2 += 256) {
        int o = e2 >> 6;
        int c = (e2 & 63) * 2;
        float v0 = Wm[o * 256 + c];
        float v1 = Wm[o * 256 + c + 1];
        __nv_bfloat16 h0 = __float2bfloat16(v0);
        __nv_bfloat16 h1 = __float2bfloat16(v1);
        __nv_bfloat16 l0 = __float2bfloat16(v0 - __bfloat162float(h0));
        __nv_bfloat16 l1 = __float2bfloat16(v1 - __bfloat162float(h1));
        __nv_bfloat162 hp, lp; hp.x = h0; hp.y = h1; lp.x = l0; lp.y = l1;
        *(uint32_t*)(Bh + o * (APITCH * 2) + c * 2) = *(uint32_t*)&hp;
        *(uint32_t*)(Bl + o * (APITCH * 2) + c * 2) = *(uint32_t*)&lp;
    }

    const int mbase = (wid & 3) * 32;
    const int nbase = (wid >> 2) * 64;

    const uint32_t aRow = (uint32_t)(mbase + (lane & 15));
    const uint32_t aColB = (uint32_t)((lane >> 4) * 16);
    const uint32_t bRow = (uint32_t)(nbase + (lane & 7) + ((lane >> 4) << 3));
    const uint32_t bColB = (uint32_t)(((lane >> 3) & 1) * 16);

    __syncthreads();

    for (int tile = blockIdx.x; tile < 2000; tile += gridDim.x) {
        if (tid < 5) {
            int m  = tile * 5 + tid;
            int mm = (m < M_MATCH) ? m : m - M_MATCH;
            int b  = b_ids[mm];
            sl[tid]  = (m < M_MATCH) ? i_ids[mm] : j_ids[mm];
            sfb[tid] = (ull)(((m < M_MATCH) ? feat_f0 : feat_f1)
                             + (size_t)b * (CF * HFD * WFD));
        }
        __syncthreads();

        for (int e = tid; e < 640; e += 256)
            t_s[e] = g_t[(size_t)(tile * 5 + (e >> 7)) * CF + (e & 127)];

        for (int e2 = tid; e2 < 8192; e2 += 256) {
            int r = e2 >> 6;
            int c = (e2 & 63) * 2;
            uint32_t hp = 0, lp = 0;
            if (r < 125) {
                int mi = r / 25;
                int w  = r - mi * 25;
                const float* fb = (const float*)sfb[mi];
                unsigned fl0 = (unsigned)sl[mi] * 3200u + (unsigned)(w * 128 + c);
                float v[2];
                #pragma unroll
                for (int q = 0; q < 2; q++) {
                    unsigned flat = fl0 + (unsigned)q;
                    unsigned ch  = flat / 120000u;
                    unsigned r1  = flat - ch * 120000u;
                    unsigned k   = r1 / 4800u;
                    unsigned pos = r1 - k * 4800u;
                    int row = (int)(pos / 80u) * 4 + (int)(k / 5u) - 2;
                    int col = (int)(pos - 80u * (pos / 80u)) * 4 + (int)(k - 5u * (k / 5u)) - 2;
                    float vv = 0.f;
                    if ((unsigned)row < (unsigned)HFD && (unsigned)col < (unsigned)WFD)
                        vv = __ldg(fb + ((size_t)ch * HFD + row) * WFD + col);
                    v[q] = vv;
                }
                __nv_bfloat16 h0 = __float2bfloat16(v[0]);
                __nv_bfloat16 h1 = __float2bfloat16(v[1]);
                __nv_bfloat16 l0 = __float2bfloat16(v[0] - __bfloat162float(h0));
                __nv_bfloat16 l1 = __float2bfloat16(v[1] - __bfloat162float(h1));
                __nv_bfloat162 hh, ll; hh.x = h0; hh.y = h1; ll.x = l0; ll.y = l1;
                hp = *(uint32_t*)&hh; lp = *(uint32_t*)&ll;
            }
            *(uint32_t*)(Ah + r * (APITCH * 2) + c * 2) = hp;
            *(uint32_t*)(Al + r * (APITCH * 2) + c * 2) = lp;
        }
        __syncthreads();

        float acc[2][8][4];
        #pragma unroll
        for (int i = 0; i < 2; i++)
            #pragma unroll
            for (int nb = 0; nb < 8; nb++) {
                acc[i][nb][0] = 0.f; acc[i][nb][1] = 0.f;
                acc[i][nb][2] = 0.f; acc[i][nb][3] = 0.f;
            }

        #pragma unroll 1
        for (int ks = 0; ks < 8; ks++) {
            const uint32_t kb = (uint32_t)(ks * 32);
            uint32_t a0_0, a0_1, a0_2, a0_3, a1_0, a1_1, a1_2, a1_3;
            uint32_t bfr[8][2];

            LDSM_X4(a0_0, a0_1, a0_2, a0_3, sAh + aRow * 272 + kb + aColB);
            LDSM_X4(a1_0, a1_1, a1_2, a1_3, sAh + (aRow + 16) * 272 + kb + aColB);
            #pragma unroll
            for (int bb = 0; bb < 4; bb++)
                LDSM_X4(bfr[2*bb][0], bfr[2*bb][1], bfr[2*bb+1][0], bfr[2*bb+1][1],
                        sBh + (bRow + bb * 16) * 272 + kb + bColB);
            #pragma unroll
            for (int nb = 0; nb < 8; nb++) {
                MMA16816(acc[0][nb], a0_0, a0_1, a0_2, a0_3, bfr[nb][0], bfr[nb][1]);
                MMA16816(acc[1][nb], a1_0, a1_1, a1_2, a1_3, bfr[nb][0], bfr[nb][1]);
            }
            #pragma unroll
            for (int bb = 0; bb < 4; bb++)
                LDSM_X4(bfr[2*bb][0], bfr[2*bb][1], bfr[2*bb+1][0], bfr[2*bb+1][1],
                        sBl + (bRow + bb * 16) * 272 + kb + bColB);
            #pragma unroll
            for (int nb = 0; nb < 8; nb++) {
                MMA16816(acc[0][nb], a0_0, a0_1, a0_2, a0_3, bfr[nb][0], bfr[nb][1]);
                MMA16816(acc[1][nb], a1_0, a1_1, a1_2, a1_3, bfr[nb][0], bfr[nb][1]);
            }
            LDSM_X4(a0_0, a0_1, a0_2, a0_3, sAl + aRow * 272 + kb + aColB);
            LDSM_X4(a1_0, a1_1, a1_2, a1_3, sAl + (aRow + 16) * 272 + kb + aColB);
            #pragma unroll
            for (int bb = 0; bb < 4; bb++)
                LDSM_X4(bfr[2*bb][0], bfr[2*bb][1], bfr[2*bb+1][0], bfr[2*bb+1][1],
                        sBh + (bRow + bb * 16) * 272 + kb + bColB);
            #pragma unroll
            for (int nb = 0; nb < 8; nb++) {
                MMA16816(acc[0][nb], a0_0, a0_1, a0_2, a0_3, bfr[nb][0], bfr[nb][1]);
                MMA16816(acc[1][nb], a1_0, a1_1, a1_2, a1_3, bfr[nb][0], bfr[nb][1]);
            }
        }

        {
            const int rl = lane >> 2;
            const int cl = 2 * (lane & 3);
            #pragma unroll
            for (int i = 0; i < 2; i++) {
                int r0 = mbase + i * 16 + rl;
                int r1 = r0 + 8;
                int mi0 = r0 / 25, w0 = r0 - mi0 * 25;
                int mi1 = r1 / 25, w1 = r1 - mi1 * 25;
                #pragma unroll
                for (int nb = 0; nb < 8; nb++) {
                    int col = nbase + nb * 8 + cl;
                    if (r0 < 125) {
                        float2 o2;
                        o2.x = acc[i][nb][0] + t_s[mi0 * 128 + col];
                        o2.y = acc[i][nb][1] + t_s[mi0 * 128 + col + 1];
                        *(float2*)&out[(size_t)(tile * 5 + mi0) * 3200 + w0 * 128 + col] = o2;
                    }
                    if (r1 < 125) {
                        float2 o2;
                        o2.x = acc[i][nb][2] + t_s[mi1 * 128 + col];
                        o2.y = acc[i][nb][3] + t_s[mi1 * 128 + col + 1];
                        *(float2*)&out[(size_t)(tile * 5 + mi1) * 3200 + w1 * 128 + col] = o2;
                    }
                }
            }
        }
        __syncthreads();
    }
}

// ---------------------------------------------------------------------------
extern "C" void kernel_launch(void* const* d_in, const int* in_sizes, int n_in,
                              void* d_out, int out_size)
{
    (void)in_sizes; (void)n_in; (void)out_size;
    const float* feat_f0 = (const float*)d_in[0];
    const float* feat_f1 = (const float*)d_in[1];
    const float* feat_c0 = (const float*)d_in[2];
    const float* feat_c1 = (const float*)d_in[3];
    const int*   b_ids   = (const int*)d_in[4];
    const int*   i_ids   = (const int*)d_in[5];
    const int*   j_ids   = (const int*)d_in[6];
    const float* Wd      = (const float*)d_in[7];
    const float* bd      = (const float*)d_in[8];
    const float* Wm      = (const float*)d_in[9];
    const float* bm      = (const float*)d_in[10];
    float* out = (float*)d_out;

    const size_t smemW = 128 * 129 * sizeof(float);
    const size_t smemP = 16384 + 32768 + 64 * sizeof(float*);
    const size_t smemF = 4 * (size_t)ABYTES + 2560 + 96;

    cudaFuncSetAttribute(wc_kernel,   cudaFuncAttributeMaxDynamicSharedMemorySize, (int)smemW);
    cudaFuncSetAttribute(proj_kernel, cudaFuncAttributeMaxDynamicSharedMemorySize, (int)smemP);
    cudaFuncSetAttribute(fine_kernel, cudaFuncAttributeMaxDynamicSharedMemorySize, (int)smemF);

    warmup_kernel<<<1, 32>>>();
    wc_kernel<<<128, 128, smemW>>>(Wd, bd, Wm, bm);
    proj_kernel<<<157, 256, smemP>>>(feat_c0, feat_c1, b_ids, i_ids, j_ids);
    fine_kernel<<<148, 256, smemF>>>(feat_f0, feat_f1, b_ids, i_ids, j_ids, Wm, out);
}

// round 7
// speedup vs baseline: 1.7364x; 1.7364x over previous
#include <cuda_runtime.h>
#include <cuda_bf16.h>
#include <cstdint>

#define M_MATCH 5000
#define TOT     10000
#define CF      128
#define CC      256
#define WW      25
#define LCELLS  4800
#define HFD     240
#define WFD     320
#define CHW     (CF * HFD * WFD)

typedef unsigned long long ull;

__device__ float g_t[TOT * CF];
__device__ float g_Wc[CC * CF];
__device__ float g_bc[CF];

__device__ __forceinline__ uint32_t smem_u32(const void* p) {
    uint32_t a;
    asm("{ .reg .u64 t; cvta.to.shared.u64 t, %1; cvt.u32.u64 %0, t; }" : "=r"(a) : "l"(p));
    return a;
}

#define LDSM_X4(r0, r1, r2, r3, addr)                                          \
    asm volatile("ldmatrix.sync.aligned.m8n8.x4.shared.b16 {%0,%1,%2,%3}, [%4];" \
        : "=r"(r0), "=r"(r1), "=r"(r2), "=r"(r3) : "r"(addr))

#define MMA16816(d, a0, a1, a2, a3, b0, b1)                                    \
    asm volatile("mma.sync.aligned.m16n8k16.row.col.f32.bf16.bf16.f32 "        \
        "{%0,%1,%2,%3}, {%4,%5,%6,%7}, {%8,%9}, {%0,%1,%2,%3};"                \
        : "+f"((d)[0]), "+f"((d)[1]), "+f"((d)[2]), "+f"((d)[3])               \
        : "r"(a0), "r"(a1), "r"(a2), "r"(a3), "r"(b0), "r"(b1))

#define CP_ASYNC4(dst, src, sz)                                                \
    asm volatile("cp.async.ca.shared.global [%0], [%1], 4, %2;"                \
        :: "r"(dst), "l"(src), "r"(sz) : "memory")
#define CP_COMMIT() asm volatile("cp.async.commit_group;" ::: "memory")
#define CP_WAIT0()  asm volatile("cp.async.wait_group 0;" ::: "memory")

__global__ void warmup_kernel() {}

// ---------------------------------------------------------------------------
// Kernel 0: Wc[c][o] = sum_j Wd[j][c]*W2[o][j];  bc = W2@bd + bm
// ---------------------------------------------------------------------------
__global__ void __launch_bounds__(128)
wc_kernel(const float* __restrict__ Wd, const float* __restrict__ bd,
          const float* __restrict__ Wm, const float* __restrict__ bm)
{
    extern __shared__ float w2T[];   // [j][129]
    const int tid = threadIdx.x;
    const int c = blockIdx.x;

    for (int it = 0; it < 128; it++)
        w2T[tid * 129 + it] = Wm[it * 256 + 128 + tid];   // w2T[j=tid][o=it]
    __syncthreads();

    float a0 = 0.f, a1 = 0.f;
    #pragma unroll 4
    for (int j = 0; j < 128; j++) {
        float w2 = w2T[j * 129 + tid];
        a0 += __ldg(&Wd[j * 256 + c])       * w2;
        a1 += __ldg(&Wd[j * 256 + c + 128]) * w2;
    }
    g_Wc[(size_t)c * 128 + tid]         = a0;
    g_Wc[(size_t)(c + 128) * 128 + tid] = a1;

    if (blockIdx.x == 0) {
        float acc = bm[tid];
        #pragma unroll 4
        for (int j = 0; j < 128; j++)
            acc += w2T[j * 129 + tid] * __ldg(&bd[j]);
        g_bc[tid] = acc;
    }
}

// ---------------------------------------------------------------------------
// Kernel 1: t[10000,128] = gather(feat_c) @ Wc + bc
// ---------------------------------------------------------------------------
__global__ void __launch_bounds__(256, 2)
proj_kernel(const float* __restrict__ feat_c0, const float* __restrict__ feat_c1,
            const int* __restrict__ b_ids, const int* __restrict__ i_ids,
            const int* __restrict__ j_ids)
{
    extern __shared__ char sraw[];
    float* A   = (float*)sraw;
    float* Wcs = (float*)(sraw + 16384);
    const float** srow = (const float**)(sraw + 16384 + 32768);

    const int tid = threadIdx.x;
    const int tile = blockIdx.x;
    const int og = tid & 15, rg = tid >> 4;
    const int o0 = og * 8;

    if (tid < 64) {
        int m = tile * 64 + tid;
        const float* p = nullptr;
        if (m < TOT) {
            int mm = (m < M_MATCH) ? m : m - M_MATCH;
            int b  = b_ids[mm];
            int l  = (m < M_MATCH) ? i_ids[mm] : j_ids[mm];
            p = ((m < M_MATCH) ? feat_c0 : feat_c1) + ((size_t)b * LCELLS + l) * CC;
        }
        srow[tid] = p;
    }

    float acc[4][8];
    {
        float4 bA = *(const float4*)&g_bc[o0];
        float4 bB = *(const float4*)&g_bc[o0 + 4];
        #pragma unroll
        for (int j = 0; j < 4; j++) {
            acc[j][0] = bA.x; acc[j][1] = bA.y; acc[j][2] = bA.z; acc[j][3] = bA.w;
            acc[j][4] = bB.x; acc[j][5] = bB.y; acc[j][6] = bB.z; acc[j][7] = bB.w;
        }
    }
    __syncthreads();

    for (int kc = 0; kc < 256; kc += 64) {
        for (int e = tid; e < 64 * 64; e += 256) {
            const float* p = srow[e >> 6];
            A[e] = p ? __ldg(p + kc + (e & 63)) : 0.f;
        }
        for (int e = tid; e < 64 * 128; e += 256)
            Wcs[e] = g_Wc[(size_t)(kc + (e >> 7)) * 128 + (e & 127)];
        __syncthreads();

        #pragma unroll 2
        for (int k = 0; k < 64; k += 4) {
            float4 fv[4];
            #pragma unroll
            for (int j = 0; j < 4; j++)
                fv[j] = *(const float4*)&A[(rg + 16 * j) * 64 + k];
            #define PSTEP(kk, COMP)                                            \
            {                                                                  \
                float4 wA = *(const float4*)&Wcs[(k + kk) * 128 + o0];         \
                float4 wB = *(const float4*)&Wcs[(k + kk) * 128 + o0 + 4];     \
                _Pragma("unroll")                                              \
                for (int j = 0; j < 4; j++) {                                  \
                    float a = fv[j].COMP;                                      \
                    acc[j][0] += a * wA.x; acc[j][1] += a * wA.y;              \
                    acc[j][2] += a * wA.z; acc[j][3] += a * wA.w;              \
                    acc[j][4] += a * wB.x; acc[j][5] += a * wB.y;              \
                    acc[j][6] += a * wB.z; acc[j][7] += a * wB.w;              \
                }                                                              \
            }
            PSTEP(0, x) PSTEP(1, y) PSTEP(2, z) PSTEP(3, w)
            #undef PSTEP
        }
        __syncthreads();
    }

    #pragma unroll
    for (int j = 0; j < 4; j++) {
        int m = tile * 64 + rg + 16 * j;
        if (m < TOT) {
            float* dst = &g_t[(size_t)m * CF + o0];
            *(float4*)dst       = make_float4(acc[j][0], acc[j][1], acc[j][2], acc[j][3]);
            *(float4*)(dst + 4) = make_float4(acc[j][4], acc[j][5], acc[j][6], acc[j][7]);
        }
    }
}

// ---------------------------------------------------------------------------
// Kernel 2: fine — cp.async staged gather + cross-tile pipeline + HMMA.
// 512 threads (16 warps, 4x4 warp grid, 32x32 warp tile), hi/lo 3-term split.
// ---------------------------------------------------------------------------
#define APITCH   136
#define ABYTES   (128 * APITCH * 2)       // 34816
#define OFF_AH   0
#define OFF_AL   34816
#define OFF_BH   69632
#define OFF_BL   104448
#define OFF_STG  139264                   // 16384 f32 = 65536 B
#define OFF_TS   204800                   // 2 x 640 f32 = 5120 B
#define OFF_NSFB 209920                   // 5 x 8 B
#define OFF_NSL  209960                   // 5 x 4 B
#define SMEM_FINE 210048

__device__ __forceinline__ void issue_tile(
    uint32_t stg_sm, uint32_t tdst_sm,
    const int* nsl, const ull* nsfb, int nxt5, int tid)
{
    #pragma unroll 4
    for (int i = 0; i < 32; i++) {
        int e = tid + (i << 9);
        int r = e >> 7, c = e & 127;
        const float* src = (const float*)nsfb[0];
        uint32_t sz = 0;
        if (r < 125) {
            int mi = r / 25;
            int w  = r - mi * 25;
            const float* fb = (const float*)nsfb[mi];
            src = fb;
            unsigned flat = (unsigned)nsl[mi] * 3200u + (unsigned)(w * 128 + c);
            unsigned ch  = flat / 120000u;
            unsigned r1  = flat - ch * 120000u;
            unsigned k   = r1 / 4800u;
            unsigned pos = r1 - k * 4800u;
            int row = (int)(pos / 80u) * 4 + (int)(k / 5u) - 2;
            int col = (int)(pos - 80u * (pos / 80u)) * 4 + (int)(k - 5u * (k / 5u)) - 2;
            if ((unsigned)row < (unsigned)HFD && (unsigned)col < (unsigned)WFD) {
                src = fb + ((size_t)ch * HFD + row) * WFD + col;
                sz = 4;
            }
        }
        CP_ASYNC4(stg_sm + (uint32_t)e * 4, src, sz);
    }
    #pragma unroll
    for (int e2 = tid; e2 < 640; e2 += 512) {
        const float* src = &g_t[(size_t)(nxt5 + (e2 >> 7)) * CF + (e2 & 127)];
        CP_ASYNC4(tdst_sm + (uint32_t)e2 * 4, src, 4u);
    }
    CP_COMMIT();
}

__global__ void __launch_bounds__(512, 1)
fine_kernel(const float* __restrict__ feat_f0, const float* __restrict__ feat_f1,
            const int* __restrict__ b_ids, const int* __restrict__ i_ids,
            const int* __restrict__ j_ids,
            const float* __restrict__ Wm, float* __restrict__ out)
{
    extern __shared__ char sraw[];
    char* Ah = sraw + OFF_AH;
    char* Al = sraw + OFF_AL;
    char* Bh = sraw + OFF_BH;
    char* Bl = sraw + OFF_BL;
    float* stg = (float*)(sraw + OFF_STG);
    float* ts0 = (float*)(sraw + OFF_TS);
    ull*   nsfb = (ull*)(sraw + OFF_NSFB);
    int*   nsl  = (int*)(sraw + OFF_NSL);

    const uint32_t sAh = smem_u32(Ah);
    const uint32_t sAl = smem_u32(Al);
    const uint32_t sBh = smem_u32(Bh);
    const uint32_t sBl = smem_u32(Bl);
    const uint32_t sStg = smem_u32(stg);
    const uint32_t sTs  = smem_u32(ts0);

    const int tid  = threadIdx.x;
    const int wid  = tid >> 5;
    const int lane = tid & 31;
    const int grid = gridDim.x;

    // B prep: W1 = merge_w[:, :128], hi/lo split
    for (int e2 = tid; e2 < 8192; e2 += 512) {
        int o = e2 >> 6;
        int c = (e2 & 63) * 2;
        float v0 = Wm[o * 256 + c];
        float v1 = Wm[o * 256 + c + 1];
        __nv_bfloat16 h0 = __float2bfloat16(v0);
        __nv_bfloat16 h1 = __float2bfloat16(v1);
        __nv_bfloat16 l0 = __float2bfloat16(v0 - __bfloat162float(h0));
        __nv_bfloat16 l1 = __float2bfloat16(v1 - __bfloat162float(h1));
        __nv_bfloat162 hp, lp; hp.x = h0; hp.y = h1; lp.x = l0; lp.y = l1;
        *(uint32_t*)(Bh + o * 272 + c * 2) = *(uint32_t*)&hp;
        *(uint32_t*)(Bl + o * 272 + c * 2) = *(uint32_t*)&lp;
    }

    const int mbase = (wid & 3) * 32;
    const int nbase = (wid >> 2) * 32;
    const uint32_t aRow  = (uint32_t)(mbase + (lane & 15));
    const uint32_t aColB = (uint32_t)((lane >> 4) * 16);
    const uint32_t bRow  = (uint32_t)(nbase + (lane & 7) + ((lane >> 4) << 3));
    const uint32_t bColB = (uint32_t)(((lane >> 3) & 1) * 16);

    // prologue: metadata + first stage issue
    if (tid < 5) {
        int m  = (int)blockIdx.x * 5 + tid;
        int mm = (m < M_MATCH) ? m : m - M_MATCH;
        int b  = b_ids[mm];
        nsl[tid]  = (m < M_MATCH) ? i_ids[mm] : j_ids[mm];
        nsfb[tid] = (ull)(((m < M_MATCH) ? feat_f0 : feat_f1) + (size_t)b * CHW);
    }
    __syncthreads();
    issue_tile(sStg, sTs, nsl, nsfb, (int)blockIdx.x * 5, tid);

    int buf = 0;

    for (int tile = blockIdx.x; tile < 2000; tile += grid) {
        const int nxt = tile + grid;

        CP_WAIT0();
        __syncthreads();                 // stage + ts[buf] ready for all

        if (tid < 5 && nxt < 2000) {     // metadata for next tile
            int m  = nxt * 5 + tid;
            int mm = (m < M_MATCH) ? m : m - M_MATCH;
            int b  = b_ids[mm];
            nsl[tid]  = (m < M_MATCH) ? i_ids[mm] : j_ids[mm];
            nsfb[tid] = (ull)(((m < M_MATCH) ? feat_f0 : feat_f1) + (size_t)b * CHW);
        }

        // convert stage -> Ah/Al (bf16 hi/lo)
        #pragma unroll 4
        for (int i = 0; i < 16; i++) {
            int e2 = tid + (i << 9);
            int r = e2 >> 6, c = (e2 & 63) * 2;
            float2 v = *(const float2*)&stg[r * 128 + c];
            __nv_bfloat16 h0 = __float2bfloat16(v.x);
            __nv_bfloat16 h1 = __float2bfloat16(v.y);
            __nv_bfloat16 l0 = __float2bfloat16(v.x - __bfloat162float(h0));
            __nv_bfloat16 l1 = __float2bfloat16(v.y - __bfloat162float(h1));
            __nv_bfloat162 hp, lp; hp.x = h0; hp.y = h1; lp.x = l0; lp.y = l1;
            *(uint32_t*)(Ah + r * 272 + c * 2) = *(uint32_t*)&hp;
            *(uint32_t*)(Al + r * 272 + c * 2) = *(uint32_t*)&lp;
        }
        __syncthreads();                 // A ready; stage free; nsl ready

        if (nxt < 2000)
            issue_tile(sStg, sTs + (uint32_t)(buf ^ 1) * 2560, nsl, nsfb, nxt * 5, tid);

        // ---- MMA: 3 terms x 8 k-steps, warp tile 32x32 ----
        float acc[2][4][4];
        #pragma unroll
        for (int i = 0; i < 2; i++)
            #pragma unroll
            for (int nb = 0; nb < 4; nb++) {
                acc[i][nb][0] = 0.f; acc[i][nb][1] = 0.f;
                acc[i][nb][2] = 0.f; acc[i][nb][3] = 0.f;
            }

        #pragma unroll 1
        for (int ks = 0; ks < 8; ks++) {
            const uint32_t kb = (uint32_t)(ks * 32);
            uint32_t a0_0, a0_1, a0_2, a0_3, a1_0, a1_1, a1_2, a1_3;
            uint32_t bfr[4][2];

            LDSM_X4(a0_0, a0_1, a0_2, a0_3, sAh + aRow * 272 + kb + aColB);
            LDSM_X4(a1_0, a1_1, a1_2, a1_3, sAh + (aRow + 16) * 272 + kb + aColB);
            #pragma unroll
            for (int bb = 0; bb < 2; bb++)
                LDSM_X4(bfr[2*bb][0], bfr[2*bb][1], bfr[2*bb+1][0], bfr[2*bb+1][1],
                        sBh + (bRow + bb * 16) * 272 + kb + bColB);
            #pragma unroll
            for (int nb = 0; nb < 4; nb++) {
                MMA16816(acc[0][nb], a0_0, a0_1, a0_2, a0_3, bfr[nb][0], bfr[nb][1]);
                MMA16816(acc[1][nb], a1_0, a1_1, a1_2, a1_3, bfr[nb][0], bfr[nb][1]);
            }
            #pragma unroll
            for (int bb = 0; bb < 2; bb++)
                LDSM_X4(bfr[2*bb][0], bfr[2*bb][1], bfr[2*bb+1][0], bfr[2*bb+1][1],
                        sBl + (bRow + bb * 16) * 272 + kb + bColB);
            #pragma unroll
            for (int nb = 0; nb < 4; nb++) {
                MMA16816(acc[0][nb], a0_0, a0_1, a0_2, a0_3, bfr[nb][0], bfr[nb][1]);
                MMA16816(acc[1][nb], a1_0, a1_1, a1_2, a1_3, bfr[nb][0], bfr[nb][1]);
            }
            LDSM_X4(a0_0, a0_1, a0_2, a0_3, sAl + aRow * 272 + kb + aColB);
            LDSM_X4(a1_0, a1_1, a1_2, a1_3, sAl + (aRow + 16) * 272 + kb + aColB);
            #pragma unroll
            for (int bb = 0; bb < 2; bb++)
                LDSM_X4(bfr[2*bb][0], bfr[2*bb][1], bfr[2*bb+1][0], bfr[2*bb+1][1],
                        sBh + (bRow + bb * 16) * 272 + kb + bColB);
            #pragma unroll
            for (int nb = 0; nb < 4; nb++) {
                MMA16816(acc[0][nb], a0_0, a0_1, a0_2, a0_3, bfr[nb][0], bfr[nb][1]);
                MMA16816(acc[1][nb], a1_0, a1_1, a1_2, a1_3, bfr[nb][0], bfr[nb][1]);
            }
        }

        // ---- epilogue: add t, store ----
        {
            const float* tsp = (const float*)(sraw + OFF_TS) + buf * 640;
            const int rl = lane >> 2;
            const int cl = 2 * (lane & 3);
            #pragma unroll
            for (int i = 0; i < 2; i++) {
                int r0 = mbase + i * 16 + rl;
                int r1 = r0 + 8;
                int mi0 = r0 / 25, w0 = r0 - mi0 * 25;
                int mi1 = r1 / 25, w1 = r1 - mi1 * 25;
                #pragma unroll
                for (int nb = 0; nb < 4; nb++) {
                    int col = nbase + nb * 8 + cl;
                    if (r0 < 125) {
                        float2 o2;
                        o2.x = acc[i][nb][0] + tsp[mi0 * 128 + col];
                        o2.y = acc[i][nb][1] + tsp[mi0 * 128 + col + 1];
                        *(float2*)&out[(size_t)(tile * 5 + mi0) * 3200 + w0 * 128 + col] = o2;
                    }
                    if (r1 < 125) {
                        float2 o2;
                        o2.x = acc[i][nb][2] + tsp[mi1 * 128 + col];
                        o2.y = acc[i][nb][3] + tsp[mi1 * 128 + col + 1];
                        *(float2*)&out[(size_t)(tile * 5 + mi1) * 3200 + w1 * 128 + col] = o2;
                    }
                }
            }
        }
        buf ^= 1;
        __syncthreads();                 // all done with A before next convert
    }
}

// ---------------------------------------------------------------------------
extern "C" void kernel_launch(void* const* d_in, const int* in_sizes, int n_in,
                              void* d_out, int out_size)
{
    (void)in_sizes; (void)n_in; (void)out_size;
    const float* feat_f0 = (const float*)d_in[0];
    const float* feat_f1 = (const float*)d_in[1];
    const float* feat_c0 = (const float*)d_in[2];
    const float* feat_c1 = (const float*)d_in[3];
    const int*   b_ids   = (const int*)d_in[4];
    const int*   i_ids   = (const int*)d_in[5];
    const int*   j_ids   = (const int*)d_in[6];
    const float* Wd      = (const float*)d_in[7];
    const float* bd      = (const float*)d_in[8];
    const float* Wm      = (const float*)d_in[9];
    const float* bm      = (const float*)d_in[10];
    float* out = (float*)d_out;

    const size_t smemW = 128 * 129 * sizeof(float);
    const size_t smemP = 16384 + 32768 + 64 * sizeof(float*);
    const size_t smemF = SMEM_FINE;

    cudaFuncSetAttribute(wc_kernel,   cudaFuncAttributeMaxDynamicSharedMemorySize, (int)smemW);
    cudaFuncSetAttribute(proj_kernel, cudaFuncAttributeMaxDynamicSharedMemorySize, (int)smemP);
    cudaFuncSetAttribute(fine_kernel, cudaFuncAttributeMaxDynamicSharedMemorySize, (int)smemF);

    warmup_kernel<<<1, 32>>>();
    wc_kernel<<<128, 128, smemW>>>(Wd, bd, Wm, bm);
    proj_kernel<<<157, 256, smemP>>>(feat_c0, feat_c1, b_ids, i_ids, j_ids);
    fine_kernel<<<148, 512, smemF>>>(feat_f0, feat_f1, b_ids, i_ids, j_ids, Wm, out);
}